// round 8
// baseline (speedup 1.0000x reference)
#include <cuda_runtime.h>
#include <cuda_fp16.h>
#include <math.h>
#include <stdint.h>

#define TOK 8192      // B*N tokens
#define CH  1024
#define HID 4096

// ---------------- scratch ----------------------------------------------------
__device__ __half g_h  [TOK * CH];            // ln1(x), fp16
__device__ float  g_f  [TOK * CH];            // real(FFT), fp32
__device__ float  g_x1 [TOK * CH];            // x + lnf(f), fp32
__device__ __half g_h2 [TOK * CH];            // ln2(x1), fp16
__device__ __half g_m  [(size_t)TOK * HID];   // gelu(...), fp16
__device__ __half g_cosh[CH * CH];            // cosine matrix [N][K], fp16 (symmetric)
__device__ __half g_w1t[(size_t)HID * CH];    // w1^T  [N=HID][K=CH], fp16
__device__ __half g_w2t[(size_t)CH * HID];    // w2^T  [N=CH][K=HID], fp16

// ---------------- helpers ----------------------------------------------------
__device__ __forceinline__ uint32_t smem_u32(const void* p) {
    uint32_t a;
    asm("{ .reg .u64 t; cvta.to.shared.u64 t, %1; cvt.u32.u64 %0, t; }" : "=r"(a) : "l"(p));
    return a;
}
__device__ __forceinline__ void cp16(uint32_t dst, const void* src) {
    asm volatile("cp.async.cg.shared.global [%0], [%1], 16;" :: "r"(dst), "l"(src));
}
#define CP_COMMIT() asm volatile("cp.async.commit_group;" ::: "memory")
#define SW128(o) ((o) ^ (((o) >> 3) & 0x70))

__device__ __forceinline__ void ldsm4(uint32_t* r, uint32_t a) {
    asm volatile("ldmatrix.sync.aligned.m8n8.x4.shared.b16 {%0,%1,%2,%3}, [%4];"
                 : "=r"(r[0]), "=r"(r[1]), "=r"(r[2]), "=r"(r[3]) : "r"(a));
}
__device__ __forceinline__ void mma16816(float* d, const uint32_t* a, const uint32_t* b) {
    asm volatile("mma.sync.aligned.m16n8k16.row.col.f32.f16.f16.f32 "
                 "{%0,%1,%2,%3}, {%4,%5,%6,%7}, {%8,%9}, {%0,%1,%2,%3};"
                 : "+f"(d[0]), "+f"(d[1]), "+f"(d[2]), "+f"(d[3])
                 : "r"(a[0]), "r"(a[1]), "r"(a[2]), "r"(a[3]), "r"(b[0]), "r"(b[1]));
}

// ---------------- small kernels ----------------------------------------------
__global__ void fill_cos_kernel() {
    int idx = blockIdx.x * blockDim.x + threadIdx.x;
    int k = idx >> 10, n = idx & 1023;
    int p = (k * n) & 1023;
    g_cosh[idx] = __float2half_rn(cosf((float)p * 6.135923151542565e-3f));
}

// out[C][R] = fp16(in[R][C])
__global__ void transpose_h(const float* __restrict__ in, __half* __restrict__ out,
                            int R, int C) {
    __shared__ float t[32][33];
    int bx = blockIdx.x * 32, by = blockIdx.y * 32;
    #pragma unroll
    for (int j = 0; j < 32; j += 8)
        t[threadIdx.y + j][threadIdx.x] = in[(size_t)(by + threadIdx.y + j) * C + bx + threadIdx.x];
    __syncthreads();
    #pragma unroll
    for (int j = 0; j < 32; j += 8)
        out[(size_t)(bx + threadIdx.y + j) * R + by + threadIdx.x] =
            __float2half_rn(t[threadIdx.x][threadIdx.y + j]);
}

__global__ void ln_kernel(const float* __restrict__ in, const float* __restrict__ g,
                          const float* __restrict__ b, __half* __restrict__ out) {
    __shared__ float sb[16];
    int row = blockIdx.x, t = threadIdx.x;
    float4 v = ((const float4*)(in + (size_t)row * CH))[t];
    float s = v.x + v.y + v.z + v.w;
    float q = v.x*v.x + v.y*v.y + v.z*v.z + v.w*v.w;
    #pragma unroll
    for (int o = 16; o; o >>= 1) { s += __shfl_xor_sync(~0u, s, o); q += __shfl_xor_sync(~0u, q, o); }
    if ((t & 31) == 0) { sb[t >> 5] = s; sb[8 + (t >> 5)] = q; }
    __syncthreads();
    s = 0.f; q = 0.f;
    #pragma unroll
    for (int i = 0; i < 8; i++) { s += sb[i]; q += sb[8 + i]; }
    float mu = s * (1.0f / CH);
    float rs = rsqrtf(q * (1.0f / CH) - mu * mu + 1e-5f);
    float4 gv = ((const float4*)g)[t];
    float4 bv = ((const float4*)b)[t];
    __half2 p0, p1;
    p0.x = __float2half_rn((v.x - mu) * rs * gv.x + bv.x);
    p0.y = __float2half_rn((v.y - mu) * rs * gv.y + bv.y);
    p1.x = __float2half_rn((v.z - mu) * rs * gv.z + bv.z);
    p1.y = __float2half_rn((v.w - mu) * rs * gv.w + bv.w);
    __half2* dst = (__half2*)(out + (size_t)row * CH);
    dst[2 * t] = p0; dst[2 * t + 1] = p1;
}

// x1 = x + lnf(f) [fp32]; h2 = fp16(ln2(x1))
__global__ void fuse2_kernel(const float* __restrict__ x,
                             const float* __restrict__ lnfg, const float* __restrict__ lnfb,
                             const float* __restrict__ ln2g, const float* __restrict__ ln2b) {
    __shared__ float sb[16];
    int row = blockIdx.x, t = threadIdx.x;
    float4 fv = ((const float4*)(g_f + (size_t)row * CH))[t];
    float s = fv.x + fv.y + fv.z + fv.w;
    float q = fv.x*fv.x + fv.y*fv.y + fv.z*fv.z + fv.w*fv.w;
    #pragma unroll
    for (int o = 16; o; o >>= 1) { s += __shfl_xor_sync(~0u, s, o); q += __shfl_xor_sync(~0u, q, o); }
    if ((t & 31) == 0) { sb[t >> 5] = s; sb[8 + (t >> 5)] = q; }
    __syncthreads();
    s = 0.f; q = 0.f;
    #pragma unroll
    for (int i = 0; i < 8; i++) { s += sb[i]; q += sb[8 + i]; }
    float mu1 = s * (1.0f / CH);
    float rs1 = rsqrtf(q * (1.0f / CH) - mu1 * mu1 + 1e-5f);

    float4 xv  = ((const float4*)(x + (size_t)row * CH))[t];
    float4 g1  = ((const float4*)lnfg)[t];
    float4 b1v = ((const float4*)lnfb)[t];
    float4 x1v;
    x1v.x = xv.x + (fv.x - mu1) * rs1 * g1.x + b1v.x;
    x1v.y = xv.y + (fv.y - mu1) * rs1 * g1.y + b1v.y;
    x1v.z = xv.z + (fv.z - mu1) * rs1 * g1.z + b1v.z;
    x1v.w = xv.w + (fv.w - mu1) * rs1 * g1.w + b1v.w;
    ((float4*)(g_x1 + (size_t)row * CH))[t] = x1v;

    __syncthreads();
    s = x1v.x + x1v.y + x1v.z + x1v.w;
    q = x1v.x*x1v.x + x1v.y*x1v.y + x1v.z*x1v.z + x1v.w*x1v.w;
    #pragma unroll
    for (int o = 16; o; o >>= 1) { s += __shfl_xor_sync(~0u, s, o); q += __shfl_xor_sync(~0u, q, o); }
    if ((t & 31) == 0) { sb[t >> 5] = s; sb[8 + (t >> 5)] = q; }
    __syncthreads();
    s = 0.f; q = 0.f;
    #pragma unroll
    for (int i = 0; i < 8; i++) { s += sb[i]; q += sb[8 + i]; }
    float mu2 = s * (1.0f / CH);
    float rs2 = rsqrtf(q * (1.0f / CH) - mu2 * mu2 + 1e-5f);

    float4 g2  = ((const float4*)ln2g)[t];
    float4 b2v = ((const float4*)ln2b)[t];
    __half2 p0, p1;
    p0.x = __float2half_rn((x1v.x - mu2) * rs2 * g2.x + b2v.x);
    p0.y = __float2half_rn((x1v.y - mu2) * rs2 * g2.y + b2v.y);
    p1.x = __float2half_rn((x1v.z - mu2) * rs2 * g2.z + b2v.z);
    p1.y = __float2half_rn((x1v.w - mu2) * rs2 * g2.w + b2v.w);
    __half2* dst = (__half2*)(g_h2 + (size_t)row * CH);
    dst[2 * t] = p0; dst[2 * t + 1] = p1;
}

// ---------------- fp16 mma.sync GEMM: C = epi(A[M,K] @ Bt[N,K]^T) ------------
// 128x256x64 block, 8 warps (64x64 warp tile, 2x4 grid), 2-stage cp.async.
// EPI: 0 plain fp32 store, 1 fp16(gelu(.+bias)), 2 fp32 .+bias+resid
template <int EPI, typename OutT>
__global__ void __launch_bounds__(256, 1)
gemm_mma(const __half* __restrict__ A, const __half* __restrict__ Bt,
         OutT* __restrict__ Cout, const float* __restrict__ bias,
         const float* __restrict__ resid, int K, int ldc) {
    constexpr int BK = 64;
    constexpr int ATILE = 128 * 64 * 2;   // 16 KB
    constexpr int BTILE = 256 * 64 * 2;   // 32 KB
    constexpr int STAGE = ATILE + BTILE;  // 48 KB

    extern __shared__ __align__(128) char smem[];
    uint32_t sbase = smem_u32(smem);

    int tid = threadIdx.x, warp = tid >> 5, lane = tid & 31;
    int wm = warp & 1, wn = warp >> 1;            // 2x4 warp grid of 64x64 tiles
    size_t bm = (size_t)blockIdx.x * 128, bn = (size_t)blockIdx.y * 256;

    float acc[4][8][4];
    #pragma unroll
    for (int i = 0; i < 4; i++)
        #pragma unroll
        for (int j = 0; j < 8; j++)
            #pragma unroll
            for (int e = 0; e < 4; e++) acc[i][j][e] = 0.f;

    auto loadStage = [&](int kt, int s) {
        int kb = kt * BK;
        uint32_t aB = sbase + s * STAGE;
        uint32_t bB = aB + ATILE;
        const __half* Ap = A + bm * K + kb;
        const __half* Bp = Bt + bn * K + kb;
        #pragma unroll
        for (int i = 0; i < 4; i++) {              // A: 128 rows x 128B
            int f = tid + i * 256;
            int r = f >> 3, c = f & 7;
            cp16(aB + SW128(r * 128 + c * 16), Ap + (size_t)r * K + c * 8);
        }
        #pragma unroll
        for (int i = 0; i < 8; i++) {              // B: 256 rows x 128B
            int f = tid + i * 256;
            int r = f >> 3, c = f & 7;
            cp16(bB + SW128(r * 128 + c * 16), Bp + (size_t)r * K + c * 8);
        }
    };

    int NT = K / BK;                               // 16 or 64
    loadStage(0, 0); CP_COMMIT();
    loadStage(1, 1); CP_COMMIT();

    for (int kt = 0; kt < NT; kt++) {
        if (kt + 1 < NT) asm volatile("cp.async.wait_group 1;" ::: "memory");
        else             asm volatile("cp.async.wait_group 0;" ::: "memory");
        __syncthreads();

        uint32_t aS = sbase + (kt & 1) * STAGE;
        uint32_t bS = aS + ATILE;
        #pragma unroll
        for (int ks = 0; ks < 4; ks++) {
            uint32_t a[4][4], b[8][2];
            #pragma unroll
            for (int mi = 0; mi < 4; mi++) {
                int row  = wm * 64 + mi * 16 + (lane & 15);
                int colh = ks * 16 + (lane >> 4) * 8;
                ldsm4(a[mi], aS + SW128(row * 128 + colh * 2));
            }
            #pragma unroll
            for (int ni = 0; ni < 8; ni += 2) {    // paired ldsm4: 2 b-frags per op
                int row  = wn * 64 + ni * 8 + (lane & 7) + ((lane >> 4) << 3);
                int colh = ks * 16 + ((lane >> 3) & 1) * 8;
                uint32_t q[4];
                ldsm4(q, bS + SW128(row * 128 + colh * 2));
                b[ni][0] = q[0]; b[ni][1] = q[1];
                b[ni + 1][0] = q[2]; b[ni + 1][1] = q[3];
            }
            #pragma unroll
            for (int mi = 0; mi < 4; mi++)
                #pragma unroll
                for (int ni = 0; ni < 8; ni++)
                    mma16816(acc[mi][ni], a[mi], b[ni]);
        }
        __syncthreads();

        if (kt + 2 < NT) {
            loadStage(kt + 2, kt & 1);
            CP_COMMIT();
        }
    }

    // direct-register epilogue
    #pragma unroll
    for (int mi = 0; mi < 4; mi++) {
        #pragma unroll
        for (int ni = 0; ni < 8; ni++) {
            size_t gr = bm + wm * 64 + mi * 16 + (lane >> 2);
            int gc = (int)bn + wn * 64 + ni * 8 + (lane & 3) * 2;
            #pragma unroll
            for (int h = 0; h < 2; h++) {
                size_t row = gr + h * 8;
                float v0 = acc[mi][ni][2 * h + 0];
                float v1 = acc[mi][ni][2 * h + 1];
                if (EPI == 1) {
                    v0 += bias[gc];     v1 += bias[gc + 1];
                    v0 = 0.5f * v0 * (1.0f + erff(v0 * 0.70710678118654752f));
                    v1 = 0.5f * v1 * (1.0f + erff(v1 * 0.70710678118654752f));
                    __half2 hv; hv.x = __float2half_rn(v0); hv.y = __float2half_rn(v1);
                    *(__half2*)((__half*)Cout + row * ldc + gc) = hv;
                } else {
                    if (EPI == 2) {
                        v0 += bias[gc]     + resid[row * ldc + gc];
                        v1 += bias[gc + 1] + resid[row * ldc + gc + 1];
                    }
                    float2 fv; fv.x = v0; fv.y = v1;
                    *(float2*)((float*)Cout + row * ldc + gc) = fv;
                }
            }
        }
    }
}

// ---------------- entry ------------------------------------------------------
extern "C" void kernel_launch(void* const* d_in, const int* in_sizes, int n_in,
                              void* d_out, int out_size) {
    const float* x    = (const float*)d_in[0];
    const float* ln1g = (const float*)d_in[1];
    const float* ln1b = (const float*)d_in[2];
    const float* lnfg = (const float*)d_in[3];
    const float* lnfb = (const float*)d_in[4];
    const float* ln2g = (const float*)d_in[5];
    const float* ln2b = (const float*)d_in[6];
    const float* w1   = (const float*)d_in[7];
    const float* b1   = (const float*)d_in[8];
    const float* w2   = (const float*)d_in[9];
    const float* b2   = (const float*)d_in[10];
    float* out = (float*)d_out;

    __half *ph, *ph2, *pm, *pcos, *pw1t, *pw2t;
    float *pf, *px1;
    cudaGetSymbolAddress((void**)&ph,   g_h);
    cudaGetSymbolAddress((void**)&pf,   g_f);
    cudaGetSymbolAddress((void**)&px1,  g_x1);
    cudaGetSymbolAddress((void**)&ph2,  g_h2);
    cudaGetSymbolAddress((void**)&pm,   g_m);
    cudaGetSymbolAddress((void**)&pcos, g_cosh);
    cudaGetSymbolAddress((void**)&pw1t, g_w1t);
    cudaGetSymbolAddress((void**)&pw2t, g_w2t);

    constexpr int SMEM = 2 * (128 + 256) * 64 * 2;   // 98304 B
    cudaFuncSetAttribute(gemm_mma<0, float>,  cudaFuncAttributeMaxDynamicSharedMemorySize, SMEM);
    cudaFuncSetAttribute(gemm_mma<1, __half>, cudaFuncAttributeMaxDynamicSharedMemorySize, SMEM);
    cudaFuncSetAttribute(gemm_mma<2, float>,  cudaFuncAttributeMaxDynamicSharedMemorySize, SMEM);

    // constants: cos matrix (symmetric, already [N][K]); transposed fp16 weights
    fill_cos_kernel<<<1024, 1024>>>();
    transpose_h<<<dim3(HID / 32, CH / 32), dim3(32, 8)>>>(w1, pw1t, CH, HID);
    transpose_h<<<dim3(CH / 32, HID / 32), dim3(32, 8)>>>(w2, pw2t, HID, CH);
    // h = fp16(ln1(x))
    ln_kernel<<<TOK, 256>>>(x, ln1g, ln1b, ph);
    // f = h @ cos^T
    gemm_mma<0, float><<<dim3(TOK / 128, CH / 256), 256, SMEM>>>(
        ph, pcos, pf, nullptr, nullptr, CH, CH);
    // x1 = x + lnf(f); h2 = fp16(ln2(x1))
    fuse2_kernel<<<TOK, 256>>>(x, lnfg, lnfb, ln2g, ln2b);
    // m = fp16(gelu(h2 @ w1 + b1))
    gemm_mma<1, __half><<<dim3(TOK / 128, HID / 256), 256, SMEM>>>(
        ph2, pw1t, pm, b1, nullptr, CH, HID);
    // out = x1 + m @ w2 + b2
    gemm_mma<2, float><<<dim3(TOK / 128, CH / 256), 256, SMEM>>>(
        pm, pw2t, out, b2, px1, HID, CH);
}

// round 9
// speedup vs baseline: 1.0435x; 1.0435x over previous
#include <cuda_runtime.h>
#include <cuda_fp16.h>
#include <math.h>
#include <stdint.h>

#define TOK 8192      // B*N tokens
#define CH  1024
#define HID 4096

// ---------------- scratch ----------------------------------------------------
__device__ __half g_h  [TOK * CH];            // ln1(x), fp16
__device__ float  g_f  [TOK * CH];            // real(FFT), fp32
__device__ float  g_x1 [TOK * CH];            // x + lnf(f), fp32
__device__ __half g_h2 [TOK * CH];            // ln2(x1), fp16
__device__ __half g_m  [(size_t)TOK * HID];   // gelu(...), fp16
__device__ __half g_cosh[CH * CH];            // cosine matrix [N][K], fp16 (symmetric)
__device__ __half g_w1t[(size_t)HID * CH];    // w1^T  [N=HID][K=CH], fp16
__device__ __half g_w2t[(size_t)CH * HID];    // w2^T  [N=CH][K=HID], fp16

// ---------------- helpers ----------------------------------------------------
__device__ __forceinline__ uint32_t smem_u32(const void* p) {
    uint32_t a;
    asm("{ .reg .u64 t; cvta.to.shared.u64 t, %1; cvt.u32.u64 %0, t; }" : "=r"(a) : "l"(p));
    return a;
}
__device__ __forceinline__ void cp16(uint32_t dst, const void* src) {
    asm volatile("cp.async.cg.shared.global [%0], [%1], 16;" :: "r"(dst), "l"(src));
}
#define CP_COMMIT() asm volatile("cp.async.commit_group;" ::: "memory")
#define SW128(o) ((o) ^ (((o) >> 3) & 0x70))

__device__ __forceinline__ void ldsm4(uint32_t* r, uint32_t a) {
    asm volatile("ldmatrix.sync.aligned.m8n8.x4.shared.b16 {%0,%1,%2,%3}, [%4];"
                 : "=r"(r[0]), "=r"(r[1]), "=r"(r[2]), "=r"(r[3]) : "r"(a));
}
__device__ __forceinline__ void mma16816(float* d, const uint32_t* a, const uint32_t* b) {
    asm volatile("mma.sync.aligned.m16n8k16.row.col.f32.f16.f16.f32 "
                 "{%0,%1,%2,%3}, {%4,%5,%6,%7}, {%8,%9}, {%0,%1,%2,%3};"
                 : "+f"(d[0]), "+f"(d[1]), "+f"(d[2]), "+f"(d[3])
                 : "r"(a[0]), "r"(a[1]), "r"(a[2]), "r"(a[3]), "r"(b[0]), "r"(b[1]));
}

// ---------------- small kernels ----------------------------------------------
__global__ void fill_cos_kernel() {
    int idx = blockIdx.x * blockDim.x + threadIdx.x;
    int k = idx >> 10, n = idx & 1023;
    int p = (k * n) & 1023;
    g_cosh[idx] = __float2half_rn(cosf((float)p * 6.135923151542565e-3f));
}

// out[C][R] = fp16(in[R][C])
__global__ void transpose_h(const float* __restrict__ in, __half* __restrict__ out,
                            int R, int C) {
    __shared__ float t[32][33];
    int bx = blockIdx.x * 32, by = blockIdx.y * 32;
    #pragma unroll
    for (int j = 0; j < 32; j += 8)
        t[threadIdx.y + j][threadIdx.x] = in[(size_t)(by + threadIdx.y + j) * C + bx + threadIdx.x];
    __syncthreads();
    #pragma unroll
    for (int j = 0; j < 32; j += 8)
        out[(size_t)(bx + threadIdx.y + j) * R + by + threadIdx.x] =
            __float2half_rn(t[threadIdx.x][threadIdx.y + j]);
}

__global__ void ln_kernel(const float* __restrict__ in, const float* __restrict__ g,
                          const float* __restrict__ b, __half* __restrict__ out) {
    __shared__ float sb[16];
    int row = blockIdx.x, t = threadIdx.x;
    float4 v = ((const float4*)(in + (size_t)row * CH))[t];
    float s = v.x + v.y + v.z + v.w;
    float q = v.x*v.x + v.y*v.y + v.z*v.z + v.w*v.w;
    #pragma unroll
    for (int o = 16; o; o >>= 1) { s += __shfl_xor_sync(~0u, s, o); q += __shfl_xor_sync(~0u, q, o); }
    if ((t & 31) == 0) { sb[t >> 5] = s; sb[8 + (t >> 5)] = q; }
    __syncthreads();
    s = 0.f; q = 0.f;
    #pragma unroll
    for (int i = 0; i < 8; i++) { s += sb[i]; q += sb[8 + i]; }
    float mu = s * (1.0f / CH);
    float rs = rsqrtf(q * (1.0f / CH) - mu * mu + 1e-5f);
    float4 gv = ((const float4*)g)[t];
    float4 bv = ((const float4*)b)[t];
    __half2 p0, p1;
    p0.x = __float2half_rn((v.x - mu) * rs * gv.x + bv.x);
    p0.y = __float2half_rn((v.y - mu) * rs * gv.y + bv.y);
    p1.x = __float2half_rn((v.z - mu) * rs * gv.z + bv.z);
    p1.y = __float2half_rn((v.w - mu) * rs * gv.w + bv.w);
    __half2* dst = (__half2*)(out + (size_t)row * CH);
    dst[2 * t] = p0; dst[2 * t + 1] = p1;
}

// x1 = x + lnf(f) [fp32]; h2 = fp16(ln2(x1))
__global__ void fuse2_kernel(const float* __restrict__ x,
                             const float* __restrict__ lnfg, const float* __restrict__ lnfb,
                             const float* __restrict__ ln2g, const float* __restrict__ ln2b) {
    __shared__ float sb[16];
    int row = blockIdx.x, t = threadIdx.x;
    float4 fv = ((const float4*)(g_f + (size_t)row * CH))[t];
    float s = fv.x + fv.y + fv.z + fv.w;
    float q = fv.x*fv.x + fv.y*fv.y + fv.z*fv.z + fv.w*fv.w;
    #pragma unroll
    for (int o = 16; o; o >>= 1) { s += __shfl_xor_sync(~0u, s, o); q += __shfl_xor_sync(~0u, q, o); }
    if ((t & 31) == 0) { sb[t >> 5] = s; sb[8 + (t >> 5)] = q; }
    __syncthreads();
    s = 0.f; q = 0.f;
    #pragma unroll
    for (int i = 0; i < 8; i++) { s += sb[i]; q += sb[8 + i]; }
    float mu1 = s * (1.0f / CH);
    float rs1 = rsqrtf(q * (1.0f / CH) - mu1 * mu1 + 1e-5f);

    float4 xv  = ((const float4*)(x + (size_t)row * CH))[t];
    float4 g1  = ((const float4*)lnfg)[t];
    float4 b1v = ((const float4*)lnfb)[t];
    float4 x1v;
    x1v.x = xv.x + (fv.x - mu1) * rs1 * g1.x + b1v.x;
    x1v.y = xv.y + (fv.y - mu1) * rs1 * g1.y + b1v.y;
    x1v.z = xv.z + (fv.z - mu1) * rs1 * g1.z + b1v.z;
    x1v.w = xv.w + (fv.w - mu1) * rs1 * g1.w + b1v.w;
    ((float4*)(g_x1 + (size_t)row * CH))[t] = x1v;

    __syncthreads();
    s = x1v.x + x1v.y + x1v.z + x1v.w;
    q = x1v.x*x1v.x + x1v.y*x1v.y + x1v.z*x1v.z + x1v.w*x1v.w;
    #pragma unroll
    for (int o = 16; o; o >>= 1) { s += __shfl_xor_sync(~0u, s, o); q += __shfl_xor_sync(~0u, q, o); }
    if ((t & 31) == 0) { sb[t >> 5] = s; sb[8 + (t >> 5)] = q; }
    __syncthreads();
    s = 0.f; q = 0.f;
    #pragma unroll
    for (int i = 0; i < 8; i++) { s += sb[i]; q += sb[8 + i]; }
    float mu2 = s * (1.0f / CH);
    float rs2 = rsqrtf(q * (1.0f / CH) - mu2 * mu2 + 1e-5f);

    float4 g2  = ((const float4*)ln2g)[t];
    float4 b2v = ((const float4*)ln2b)[t];
    __half2 p0, p1;
    p0.x = __float2half_rn((x1v.x - mu2) * rs2 * g2.x + b2v.x);
    p0.y = __float2half_rn((x1v.y - mu2) * rs2 * g2.y + b2v.y);
    p1.x = __float2half_rn((x1v.z - mu2) * rs2 * g2.z + b2v.z);
    p1.y = __float2half_rn((x1v.w - mu2) * rs2 * g2.w + b2v.w);
    __half2* dst = (__half2*)(g_h2 + (size_t)row * CH);
    dst[2 * t] = p0; dst[2 * t + 1] = p1;
}

// ---------------- fp16 mma.sync GEMM: C = epi(A[M,K] @ Bt[N,K]^T) ------------
// 128x256x64 block, 8 warps (64x64 warp tile), 3-stage cp.async, 1 sync/iter.
// EPI: 0 plain fp32 store, 1 fp16(gelu(.+bias)), 2 fp32 .+bias+resid
template <int EPI, typename OutT>
__global__ void __launch_bounds__(256, 1)
gemm_mma(const __half* __restrict__ A, const __half* __restrict__ Bt,
         OutT* __restrict__ Cout, const float* __restrict__ bias,
         const float* __restrict__ resid, int K, int ldc) {
    constexpr int BK = 64, STG = 3;
    constexpr int ATILE = 128 * 64 * 2;   // 16 KB
    constexpr int BTILE = 256 * 64 * 2;   // 32 KB
    constexpr int STAGE = ATILE + BTILE;  // 48 KB

    extern __shared__ __align__(128) char smem[];
    uint32_t sbase = smem_u32(smem);

    int tid = threadIdx.x, warp = tid >> 5, lane = tid & 31;
    int wm = warp & 1, wn = warp >> 1;            // 2x4 warp grid of 64x64 tiles
    size_t bm = (size_t)blockIdx.x * 128, bn = (size_t)blockIdx.y * 256;

    float acc[4][8][4];
    #pragma unroll
    for (int i = 0; i < 4; i++)
        #pragma unroll
        for (int j = 0; j < 8; j++)
            #pragma unroll
            for (int e = 0; e < 4; e++) acc[i][j][e] = 0.f;

    auto loadStage = [&](int kt, int s) {
        int kb = kt * BK;
        uint32_t aB = sbase + s * STAGE;
        uint32_t bB = aB + ATILE;
        const __half* Ap = A + bm * K + kb;
        const __half* Bp = Bt + bn * K + kb;
        #pragma unroll
        for (int i = 0; i < 4; i++) {              // A: 128 rows x 128B
            int f = tid + i * 256;
            int r = f >> 3, c = f & 7;
            cp16(aB + SW128(r * 128 + c * 16), Ap + (size_t)r * K + c * 8);
        }
        #pragma unroll
        for (int i = 0; i < 8; i++) {              // B: 256 rows x 128B
            int f = tid + i * 256;
            int r = f >> 3, c = f & 7;
            cp16(bB + SW128(r * 128 + c * 16), Bp + (size_t)r * K + c * 8);
        }
    };

    int NT = K / BK;                               // 16 or 64
    loadStage(0, 0); CP_COMMIT();
    loadStage(1, 1); CP_COMMIT();

    for (int kt = 0; kt < NT; kt++) {
        // drain so stage kt is complete; g(kt+1) may stay pending
        if (kt + 1 < NT) asm volatile("cp.async.wait_group 1;" ::: "memory");
        else             asm volatile("cp.async.wait_group 0;" ::: "memory");
        __syncthreads();   // all warps done with iter kt-1's slot before it's rewritten

        // prefetch kt+2 into slot (kt+2)%3 == slot of iter kt-1 (safe post-sync);
        // overlaps with compute below
        if (kt + 2 < NT) {
            loadStage(kt + 2, (kt + 2) % STG);
            CP_COMMIT();
        }

        uint32_t aS = sbase + (kt % STG) * STAGE;
        uint32_t bS = aS + ATILE;
        #pragma unroll
        for (int ks = 0; ks < 4; ks++) {
            uint32_t a[4][4], b[8][2];
            #pragma unroll
            for (int mi = 0; mi < 4; mi++) {
                int row  = wm * 64 + mi * 16 + (lane & 15);
                int colh = ks * 16 + (lane >> 4) * 8;
                ldsm4(a[mi], aS + SW128(row * 128 + colh * 2));
            }
            #pragma unroll
            for (int ni = 0; ni < 8; ni += 2) {    // paired ldsm4: 2 b-frags per op
                int row  = wn * 64 + ni * 8 + (lane & 7) + ((lane >> 4) << 3);
                int colh = ks * 16 + ((lane >> 3) & 1) * 8;
                uint32_t q[4];
                ldsm4(q, bS + SW128(row * 128 + colh * 2));
                b[ni][0] = q[0]; b[ni][1] = q[1];
                b[ni + 1][0] = q[2]; b[ni + 1][1] = q[3];
            }
            #pragma unroll
            for (int mi = 0; mi < 4; mi++)
                #pragma unroll
                for (int ni = 0; ni < 8; ni++)
                    mma16816(acc[mi][ni], a[mi], b[ni]);
        }
    }

    // direct-register epilogue
    #pragma unroll
    for (int mi = 0; mi < 4; mi++) {
        #pragma unroll
        for (int ni = 0; ni < 8; ni++) {
            size_t gr = bm + wm * 64 + mi * 16 + (lane >> 2);
            int gc = (int)bn + wn * 64 + ni * 8 + (lane & 3) * 2;
            #pragma unroll
            for (int h = 0; h < 2; h++) {
                size_t row = gr + h * 8;
                float v0 = acc[mi][ni][2 * h + 0];
                float v1 = acc[mi][ni][2 * h + 1];
                if (EPI == 1) {
                    v0 += bias[gc];     v1 += bias[gc + 1];
                    v0 = 0.5f * v0 * (1.0f + erff(v0 * 0.70710678118654752f));
                    v1 = 0.5f * v1 * (1.0f + erff(v1 * 0.70710678118654752f));
                    __half2 hv; hv.x = __float2half_rn(v0); hv.y = __float2half_rn(v1);
                    *(__half2*)((__half*)Cout + row * ldc + gc) = hv;
                } else {
                    if (EPI == 2) {
                        v0 += bias[gc]     + resid[row * ldc + gc];
                        v1 += bias[gc + 1] + resid[row * ldc + gc + 1];
                    }
                    float2 fv; fv.x = v0; fv.y = v1;
                    *(float2*)((float*)Cout + row * ldc + gc) = fv;
                }
            }
        }
    }
}

// ---------------- entry ------------------------------------------------------
extern "C" void kernel_launch(void* const* d_in, const int* in_sizes, int n_in,
                              void* d_out, int out_size) {
    const float* x    = (const float*)d_in[0];
    const float* ln1g = (const float*)d_in[1];
    const float* ln1b = (const float*)d_in[2];
    const float* lnfg = (const float*)d_in[3];
    const float* lnfb = (const float*)d_in[4];
    const float* ln2g = (const float*)d_in[5];
    const float* ln2b = (const float*)d_in[6];
    const float* w1   = (const float*)d_in[7];
    const float* b1   = (const float*)d_in[8];
    const float* w2   = (const float*)d_in[9];
    const float* b2   = (const float*)d_in[10];
    float* out = (float*)d_out;

    __half *ph, *ph2, *pm, *pcos, *pw1t, *pw2t;
    float *pf, *px1;
    cudaGetSymbolAddress((void**)&ph,   g_h);
    cudaGetSymbolAddress((void**)&pf,   g_f);
    cudaGetSymbolAddress((void**)&px1,  g_x1);
    cudaGetSymbolAddress((void**)&ph2,  g_h2);
    cudaGetSymbolAddress((void**)&pm,   g_m);
    cudaGetSymbolAddress((void**)&pcos, g_cosh);
    cudaGetSymbolAddress((void**)&pw1t, g_w1t);
    cudaGetSymbolAddress((void**)&pw2t, g_w2t);

    constexpr int SMEM = 3 * (128 + 256) * 64 * 2;   // 147456 B
    cudaFuncSetAttribute(gemm_mma<0, float>,  cudaFuncAttributeMaxDynamicSharedMemorySize, SMEM);
    cudaFuncSetAttribute(gemm_mma<1, __half>, cudaFuncAttributeMaxDynamicSharedMemorySize, SMEM);
    cudaFuncSetAttribute(gemm_mma<2, float>,  cudaFuncAttributeMaxDynamicSharedMemorySize, SMEM);

    // constants: cos matrix (symmetric, already [N][K]); transposed fp16 weights
    fill_cos_kernel<<<1024, 1024>>>();
    transpose_h<<<dim3(HID / 32, CH / 32), dim3(32, 8)>>>(w1, pw1t, CH, HID);
    transpose_h<<<dim3(CH / 32, HID / 32), dim3(32, 8)>>>(w2, pw2t, HID, CH);
    // h = fp16(ln1(x))
    ln_kernel<<<TOK, 256>>>(x, ln1g, ln1b, ph);
    // f = h @ cos^T
    gemm_mma<0, float><<<dim3(TOK / 128, CH / 256), 256, SMEM>>>(
        ph, pcos, pf, nullptr, nullptr, CH, CH);
    // x1 = x + lnf(f); h2 = fp16(ln2(x1))
    fuse2_kernel<<<TOK, 256>>>(x, lnfg, lnfb, ln2g, ln2b);
    // m = fp16(gelu(h2 @ w1 + b1))
    gemm_mma<1, __half><<<dim3(TOK / 128, HID / 256), 256, SMEM>>>(
        ph2, pw1t, pm, b1, nullptr, CH, HID);
    // out = x1 + m @ w2 + b2
    gemm_mma<2, float><<<dim3(TOK / 128, CH / 256), 256, SMEM>>>(
        pm, pw2t, out, b2, px1, HID, CH);
}